// round 12
// baseline (speedup 1.0000x reference)
#include <cuda_runtime.h>
#include <math.h>
#include <stdint.h>

// Problem constants (fixed by the dataset instance)
#define M_TOK 16384   // B*S = 4*4096
#define DDIM  1024    // model dim = H*Khead = 16*64
// windows: 8 of 512 tokens; heads: 16 of dim 64

// Static device scratch (allocation-free rule): 3 x 64MB
__device__ float g_Q[(size_t)M_TOK * DDIM];
__device__ float g_K[(size_t)M_TOK * DDIM];
__device__ float g_V[(size_t)M_TOK * DDIM];

// Raw fp32 fed to tf32 MMA == truncation to tf32 (HW ignores low mantissa
// bits).
__device__ __forceinline__ void mma_tf32(
    float& d0, float& d1, float& d2, float& d3,
    uint32_t a0, uint32_t a1, uint32_t a2, uint32_t a3,
    uint32_t b0, uint32_t b1)
{
    asm volatile(
        "mma.sync.aligned.m16n8k8.row.col.f32.tf32.tf32.f32 "
        "{%0,%1,%2,%3}, {%4,%5,%6,%7}, {%8,%9}, {%0,%1,%2,%3};"
        : "+f"(d0), "+f"(d1), "+f"(d2), "+f"(d3)
        : "r"(a0), "r"(a1), "r"(a2), "r"(a3), "r"(b0), "r"(b1));
}

__device__ __forceinline__ void cp_async16(void* smem_dst, const void* gsrc) {
    uint32_t s = (uint32_t)__cvta_generic_to_shared(smem_dst);
    asm volatile("cp.async.cg.shared.global [%0], [%1], 16;" :: "r"(s), "l"(gsrc));
}
__device__ __forceinline__ void cp_commit() {
    asm volatile("cp.async.commit_group;");
}
__device__ __forceinline__ void cp_wait_all() {
    asm volatile("cp.async.wait_group 0;");
}
__device__ __forceinline__ void cp_wait_1() {
    asm volatile("cp.async.wait_group 1;");
}

// ---------------------------------------------------------------------------
// TF32 tensor-core GEMM, 3-output variant: z = blockIdx.z selects (Bm, bias,
// C). C[M,1024] = A[M,1024] @ Bm[1024,1024] + bias (+ resid).
// 128x128x32 block tile, 256 threads = 8 warps (4 m x 2 n).
// 3-stage cp.async pipeline: tile t computes while t+1, t+2 load.
// dyn smem: 3*(128*36 + 32*136)*4 = 107520 B
// ---------------------------------------------------------------------------
#define GEMM_SMEM_BYTES ((3 * 128 * 36 + 3 * 32 * 136) * 4)

__global__ __launch_bounds__(256) void tf32_gemm3_kernel(
    const float* __restrict__ A,
    const float* __restrict__ B0, const float* __restrict__ B1,
    const float* __restrict__ B2,
    const float* __restrict__ bias0, const float* __restrict__ bias1,
    const float* __restrict__ bias2,
    const float* __restrict__ resid,
    float* __restrict__ C0, float* __restrict__ C1, float* __restrict__ C2)
{
    extern __shared__ float gsm[];
    float (*As)[128][36] = (float(*)[128][36])gsm;               // [3][128][36]
    float (*Bs)[32][136] = (float(*)[32][136])(gsm + 3 * 128 * 36);

    int z = blockIdx.z;
    const float* Bm   = (z == 0) ? B0 : (z == 1) ? B1 : B2;
    const float* bias = (z == 0) ? bias0 : (z == 1) ? bias1 : bias2;
    float* C          = (z == 0) ? C0 : (z == 1) ? C1 : C2;

    int tid = threadIdx.x;
    int lane = tid & 31, wid = tid >> 5;
    int warp_m = wid & 3;
    int warp_n = wid >> 2;
    int gid = lane >> 2, tig = lane & 3;

    int row0 = blockIdx.y << 7;
    int col0 = blockIdx.x << 7;

    float acc[2][8][4];
#pragma unroll
    for (int mt = 0; mt < 2; mt++)
#pragma unroll
        for (int nt = 0; nt < 8; nt++)
#pragma unroll
            for (int r = 0; r < 4; r++) acc[mt][nt][r] = 0.f;

    int rowA = tid >> 1;
    int colA0 = (tid & 1) << 4;        // 0 or 16 floats
    int rowB = tid >> 3;
    int colB0 = (tid & 7) << 4;        // 0..112 step 16

    const float* Ag = A + (size_t)(row0 + rowA) * DDIM + colA0;
    const float* Bg = Bm + (size_t)rowB * DDIM + col0 + colB0;

    // prologue: stage tiles 0 and 1 as separate commit groups
#pragma unroll
    for (int st = 0; st < 2; st++) {
        int k0 = st << 5;
#pragma unroll
        for (int p = 0; p < 4; p++) {
            cp_async16(&As[st][rowA][colA0 + p * 4], Ag + k0 + p * 4);
            cp_async16(&Bs[st][rowB][colB0 + p * 4],
                       Bg + (size_t)k0 * DDIM + p * 4);
        }
        cp_commit();
    }

    for (int t = 0; t < 32; t++) {
        // stage t ready: with 2 younger groups possibly pending use wait 1;
        // tail iters have fewer pending so wait 0 guarantees residency.
        if (t < 30) cp_wait_1(); else cp_wait_all();
        __syncthreads();   // all warps done reading buffer (t+2)%3's old data

        if (t + 2 < 32) {
            int sn = (t + 2) % 3;
            int k0n = (t + 2) << 5;
#pragma unroll
            for (int p = 0; p < 4; p++) {
                cp_async16(&As[sn][rowA][colA0 + p * 4], Ag + k0n + p * 4);
                cp_async16(&Bs[sn][rowB][colB0 + p * 4],
                           Bg + (size_t)k0n * DDIM + p * 4);
            }
            cp_commit();
        }

        int s = t % 3;
#pragma unroll
        for (int ks = 0; ks < 4; ks++) {
            int kk = ks << 3;
            uint32_t af[2][4];
            int mrow = (warp_m << 5) + gid;
#pragma unroll
            for (int mt = 0; mt < 2; mt++) {
                int r = mrow + (mt << 4);
                af[mt][0] = __float_as_uint(As[s][r][kk + tig]);
                af[mt][1] = __float_as_uint(As[s][r + 8][kk + tig]);
                af[mt][2] = __float_as_uint(As[s][r][kk + tig + 4]);
                af[mt][3] = __float_as_uint(As[s][r + 8][kk + tig + 4]);
            }
            uint32_t bf[8][2];
            int nbase = (warp_n << 6) + gid;
#pragma unroll
            for (int nt = 0; nt < 8; nt++) {
                int c = nbase + (nt << 3);
                bf[nt][0] = __float_as_uint(Bs[s][kk + tig][c]);
                bf[nt][1] = __float_as_uint(Bs[s][kk + tig + 4][c]);
            }
#pragma unroll
            for (int mt = 0; mt < 2; mt++)
#pragma unroll
                for (int nt = 0; nt < 8; nt++)
                    mma_tf32(acc[mt][nt][0], acc[mt][nt][1],
                             acc[mt][nt][2], acc[mt][nt][3],
                             af[mt][0], af[mt][1], af[mt][2], af[mt][3],
                             bf[nt][0], bf[nt][1]);
        }
    }

#pragma unroll
    for (int mt = 0; mt < 2; mt++) {
#pragma unroll
        for (int nt = 0; nt < 8; nt++) {
            int col = col0 + (warp_n << 6) + (nt << 3) + (tig << 1);
            float bx = bias[col], by = bias[col + 1];
#pragma unroll
            for (int h = 0; h < 2; h++) {
                size_t row = (size_t)row0 + (warp_m << 5) + (mt << 4) + gid + (h << 3);
                float2 o;
                o.x = acc[mt][nt][2 * h + 0] + bx;
                o.y = acc[mt][nt][2 * h + 1] + by;
                if (resid) {
                    float2 rv = *(const float2*)(resid + row * DDIM + col);
                    o.x += rv.x; o.y += rv.y;
                }
                *(float2*)(C + row * DDIM + col) = o;
            }
        }
    }
}

// ---------------------------------------------------------------------------
// Tensor-core windowed attention, 32 q-rows per block for 2 CTAs/SM.
// 512 threads = 16 warps: warp w -> n-tile (w&7), m-tile mg=(w>>3) (16 rows).
// Q staging tile overlays KV stage-1 buffer (consumed into af regs before
// that buffer's first prefetch).
// Smem: Ssm[32][516] + KV[2][64][68] = 100864 B -> 2 blocks/SM.
// ---------------------------------------------------------------------------
#define SS_LD 516
#define QK_LD 68
#define ATTN_SMEM_BYTES ((32 * SS_LD + 2 * 64 * QK_LD) * 4)

__global__ __launch_bounds__(512, 2) void attn_mma_kernel(
    const float* __restrict__ Km, const float* __restrict__ V,
    float* __restrict__ QC)   // Q in, context out (in-place)
{
    extern __shared__ float sm[];
    float* Ssm = sm;                        // [32][516]
    float* KV0 = sm + 32 * SS_LD;           // [64][68] stage 0
    float* KV1 = KV0 + 64 * QK_LD;          // [64][68] stage 1 (Q overlay)

    int tid = threadIdx.x;
    int lane = tid & 31;
    int w = tid >> 5;
    int gid = lane >> 2, tig = lane & 3;
    int nt = w & 7;
    int mg = w >> 3;                        // 0..1
    int mrow = mg << 4;

    int hid = blockIdx.y;                   // (b, win, h)
    int b = hid >> 7;
    int wn = (hid >> 4) & 7;
    int h = hid & 15;
    int t0 = b * 4096 + wn * 512;
    int hcol = h << 6;
    int qbase = blockIdx.x << 5;            // 32 q-rows per block

    int r = tid >> 3;                       // 0..63 KV staging row
    int c0 = (tid & 7) << 3;                // 0..56 staging col (8 floats)

    // ---- stage Q (32x64) into KV1 + prefetch K tile 0 into KV0 ----
    {
        int qr = tid >> 4;                  // 0..31
        int qc = (tid & 15) << 2;           // 0..60
        float4 qv = *(const float4*)(QC + (size_t)(t0 + qbase + qr) * DDIM + hcol + qc);
        const float* ksrc = Km + (size_t)(t0 + r) * DDIM + hcol + c0;
        cp_async16(&KV0[r * QK_LD + c0], ksrc);
        cp_async16(&KV0[r * QK_LD + c0 + 4], ksrc + 4);
        cp_commit();
        *(float4*)&KV1[qr * QK_LD + qc] = qv;
    }
    __syncthreads();                        // Q visible

    // ---- hoist Q A-fragments from KV1 (k-invariant across key tiles) ----
    uint32_t af[8][4];
#pragma unroll
    for (int ks = 0; ks < 8; ks++) {
        int kk = ks << 3;
        af[ks][0] = __float_as_uint(KV1[(mrow + gid) * QK_LD + kk + tig]);
        af[ks][1] = __float_as_uint(KV1[(mrow + gid + 8) * QK_LD + kk + tig]);
        af[ks][2] = __float_as_uint(KV1[(mrow + gid) * QK_LD + kk + tig + 4]);
        af[ks][3] = __float_as_uint(KV1[(mrow + gid + 8) * QK_LD + kk + tig + 4]);
    }
    cp_wait_all();
    __syncthreads();                        // af done (KV1 free), K0 visible

    // ---- scores S[32][512] = Q K^T via mma, pipelined over 8 key tiles ----
    for (int kt = 0; kt < 8; kt++) {
        float* cur = (kt & 1) ? KV1 : KV0;
        if (kt < 7) {
            float* nxt = (kt & 1) ? KV0 : KV1;
            const float* src = Km + (size_t)(t0 + (kt + 1) * 64 + r) * DDIM + hcol + c0;
            cp_async16(&nxt[r * QK_LD + c0], src);
            cp_async16(&nxt[r * QK_LD + c0 + 4], src + 4);
            cp_commit();
        }
        float s0 = 0.f, s1 = 0.f, s2 = 0.f, s3 = 0.f;
#pragma unroll
        for (int ks = 0; ks < 8; ks++) {
            int kk = ks << 3;
            uint32_t b0 = __float_as_uint(cur[((nt << 3) + gid) * QK_LD + kk + tig]);
            uint32_t b1 = __float_as_uint(cur[((nt << 3) + gid) * QK_LD + kk + tig + 4]);
            mma_tf32(s0, s1, s2, s3,
                     af[ks][0], af[ks][1], af[ks][2], af[ks][3], b0, b1);
        }
        {
            int row = mrow + gid;
            int col = kt * 64 + (nt << 3) + (tig << 1);
            *(float2*)&Ssm[row * SS_LD + col] = make_float2(s0, s1);
            *(float2*)&Ssm[(row + 8) * SS_LD + col] = make_float2(s2, s3);
        }
        cp_wait_all();
        __syncthreads();
    }

    // prefetch V tile 0 into KV0 (both buffers free), overlaps softmax
    {
        const float* src = V + (size_t)(t0 + r) * DDIM + hcol + c0;
        cp_async16(&KV0[r * QK_LD + c0], src);
        cp_async16(&KV0[r * QK_LD + c0 + 4], src + 4);
        cp_commit();
    }

    // ---- softmax over 512 keys per row (2 rows per warp), scale 0.125 ----
    {
#pragma unroll
        for (int q = 0; q < 2; q++) {
            int rr = (w << 1) + q;
            float vals[16];
            float m = -1e30f;
#pragma unroll
            for (int t = 0; t < 16; t++) {
                vals[t] = Ssm[rr * SS_LD + lane + 32 * t];
                m = fmaxf(m, vals[t]);
            }
#pragma unroll
            for (int off = 16; off > 0; off >>= 1)
                m = fmaxf(m, __shfl_xor_sync(0xffffffffu, m, off));
            float s = 0.f;
#pragma unroll
            for (int t = 0; t < 16; t++) {
                float e = __expf((vals[t] - m) * 0.125f);
                vals[t] = e;
                s += e;
            }
#pragma unroll
            for (int off = 16; off > 0; off >>= 1)
                s += __shfl_xor_sync(0xffffffffu, s, off);
            float inv = 1.0f / s;
#pragma unroll
            for (int t = 0; t < 16; t++)
                Ssm[rr * SS_LD + lane + 32 * t] = vals[t] * inv;
        }
    }
    cp_wait_all();
    __syncthreads();   // V0 ready; softmax writes visible

    // ---- O[32][64] = P[32][512] @ V[512][64], pipelined ----
    float o0 = 0.f, o1 = 0.f, o2 = 0.f, o3 = 0.f;

    for (int kt = 0; kt < 8; kt++) {
        float* cur = (kt & 1) ? KV1 : KV0;
        if (kt < 7) {
            float* nxt = (kt & 1) ? KV0 : KV1;
            const float* src = V + (size_t)(t0 + (kt + 1) * 64 + r) * DDIM + hcol + c0;
            cp_async16(&nxt[r * QK_LD + c0], src);
            cp_async16(&nxt[r * QK_LD + c0 + 4], src + 4);
            cp_commit();
        }
#pragma unroll
        for (int ks = 0; ks < 8; ks++) {
            int kk = ks << 3;
            uint32_t b0 = __float_as_uint(cur[(kk + tig) * QK_LD + (nt << 3) + gid]);
            uint32_t b1 = __float_as_uint(cur[(kk + tig + 4) * QK_LD + (nt << 3) + gid]);
            int kc = kt * 64 + kk;
            uint32_t a0 = __float_as_uint(Ssm[(mrow + gid) * SS_LD + kc + tig]);
            uint32_t a1 = __float_as_uint(Ssm[(mrow + gid + 8) * SS_LD + kc + tig]);
            uint32_t a2 = __float_as_uint(Ssm[(mrow + gid) * SS_LD + kc + tig + 4]);
            uint32_t a3 = __float_as_uint(Ssm[(mrow + gid + 8) * SS_LD + kc + tig + 4]);
            mma_tf32(o0, o1, o2, o3, a0, a1, a2, a3, b0, b1);
        }
        cp_wait_all();
        __syncthreads();
    }

    // ---- store context in-place over Q ----
    {
        size_t row = (size_t)t0 + qbase + mrow + gid;
        int col = hcol + (nt << 3) + (tig << 1);
        *(float2*)(QC + row * DDIM + col) = make_float2(o0, o1);
        *(float2*)(QC + (row + 8) * DDIM + col) = make_float2(o2, o3);
    }
}

// ---------------------------------------------------------------------------
// LayerNorm per row (1024 elems), keras eps = 1e-3. One block per row.
// ---------------------------------------------------------------------------
__global__ __launch_bounds__(256) void ln_kernel(
    const float* __restrict__ Y, const float* __restrict__ gamma,
    const float* __restrict__ beta, float* __restrict__ out)
{
    int row = blockIdx.x;
    int tid = threadIdx.x;
    const float* y = Y + (size_t)row * DDIM;

    float4 v = *(const float4*)(y + tid * 4);
    float s  = v.x + v.y + v.z + v.w;
    float sq = v.x * v.x + v.y * v.y + v.z * v.z + v.w * v.w;

#pragma unroll
    for (int off = 16; off > 0; off >>= 1) {
        s  += __shfl_xor_sync(0xffffffffu, s, off);
        sq += __shfl_xor_sync(0xffffffffu, sq, off);
    }
    __shared__ float ss[8], ssq[8];
    int lane = tid & 31, wid = tid >> 5;
    if (lane == 0) { ss[wid] = s; ssq[wid] = sq; }
    __syncthreads();
    float S = 0.f, SQ = 0.f;
#pragma unroll
    for (int i = 0; i < 8; i++) { S += ss[i]; SQ += ssq[i]; }

    float mu  = S * (1.0f / 1024.0f);
    float var = SQ * (1.0f / 1024.0f) - mu * mu;
    float inv = rsqrtf(var + 1e-3f);

    float4 g  = *(const float4*)(gamma + tid * 4);
    float4 be = *(const float4*)(beta + tid * 4);
    float4 o;
    o.x = (v.x - mu) * inv * g.x + be.x;
    o.y = (v.y - mu) * inv * g.y + be.y;
    o.z = (v.z - mu) * inv * g.z + be.z;
    o.w = (v.w - mu) * inv * g.w + be.w;
    *(float4*)(out + (size_t)row * DDIM + tid * 4) = o;
}

// ---------------------------------------------------------------------------
extern "C" void kernel_launch(void* const* d_in, const int* in_sizes, int n_in,
                              void* d_out, int out_size)
{
    const float* x     = (const float*)d_in[0];
    const float* Wq    = (const float*)d_in[1];
    const float* bq    = (const float*)d_in[2];
    const float* Wk    = (const float*)d_in[3];
    const float* bk    = (const float*)d_in[4];
    const float* Wv    = (const float*)d_in[5];
    const float* bv    = (const float*)d_in[6];
    const float* Wo    = (const float*)d_in[7];
    const float* bo    = (const float*)d_in[8];
    const float* gamma = (const float*)d_in[9];
    const float* beta  = (const float*)d_in[10];
    float* out = (float*)d_out;
    (void)in_sizes; (void)n_in; (void)out_size;

    float *Qp, *Kp, *Vp;
    cudaGetSymbolAddress((void**)&Qp, g_Q);
    cudaGetSymbolAddress((void**)&Kp, g_K);
    cudaGetSymbolAddress((void**)&Vp, g_V);

    cudaFuncSetAttribute(tf32_gemm3_kernel,
                         cudaFuncAttributeMaxDynamicSharedMemorySize, GEMM_SMEM_BYTES);
    cudaFuncSetAttribute(attn_mma_kernel,
                         cudaFuncAttributeMaxDynamicSharedMemorySize, ATTN_SMEM_BYTES);

    // Q, K, V in one launch: z selects weights/bias/output
    tf32_gemm3_kernel<<<dim3(8, 128, 3), 256, GEMM_SMEM_BYTES>>>(
        x, Wq, Wk, Wv, bq, bk, bv, nullptr, Qp, Kp, Vp);

    // ctx overwrites Q in-place; grid: 16 q-tiles of 32 x 512 heads
    attn_mma_kernel<<<dim3(16, 512), 512, ATTN_SMEM_BYTES>>>(Kp, Vp, Qp);

    // Y = ctx @ Wo + bo + x   (write Y into g_K, dead after attention)
    tf32_gemm3_kernel<<<dim3(8, 128, 1), 256, GEMM_SMEM_BYTES>>>(
        Qp, Wo, Wo, Wo, bo, bo, bo, x, Kp, Kp, Kp);

    ln_kernel<<<M_TOK, 256>>>(Kp, gamma, beta, out);
}